// round 9
// baseline (speedup 1.0000x reference)
#include <cuda_runtime.h>
#include <cuda_bf16.h>

#define B_ROWS   16384
#define CWIN     10
#define KNEG     10
#define NSCORE   (KNEG + 1)
#define NROW     (CWIN + 1 + KNEG)    // 21 staged embedding rows per batch-row
#define DIM      128
#define VEC      (DIM / 4)            // 32 float4 per row -> 1 per lane
#define WARPS_PER_BLOCK 2
#define NTHREADS (WARPS_PER_BLOCK * 32)          // 64
#define ROWS_PER_WARP 4
#define ROWS_PER_BLOCK (WARPS_PER_BLOCK * ROWS_PER_WARP) // 8
#define NBLOCKS  (B_ROWS / ROWS_PER_BLOCK)               // 2048
#define EPS      1e-9f
#define FULLM    0xffffffffu

// Scratch for deterministic reduction (no allocations allowed).
__device__ float        g_block_partial[NBLOCKS];
__device__ unsigned int g_done_counter = 0u;

__device__ __forceinline__ void cp16(void* smem_dst, const void* gsrc) {
    unsigned s = (unsigned)__cvta_generic_to_shared(smem_dst);
    asm volatile("cp.async.cg.shared.global [%0], [%1], 16;\n"
                 :: "r"(s), "l"(gsrc) : "memory");
}

__global__ __launch_bounds__(NTHREADS) void cbow_loss_kernel(
    const int*   __restrict__ ctx,      // [B, CWIN]
    const int*   __restrict__ tgt,      // [B]
    const int*   __restrict__ neg,      // [B, KNEG]
    const float* __restrict__ in_emb,   // [VOCAB, DIM]
    const float* __restrict__ out_emb,  // [VOCAB, DIM]
    float*       __restrict__ out)
{
    // [warp][double-buffer][staged row][lane] : 2*2*21*32*16 = 43008 B
    __shared__ float4 sh[WARPS_PER_BLOCK][2][NROW][VEC];

    const int warp = threadIdx.x >> 5;
    const int lane = threadIdx.x & 31;
    const int rbase = blockIdx.x * ROWS_PER_BLOCK + warp * ROWS_PER_WARP;

    const float4* __restrict__ in4  = (const float4*)in_emb;
    const float4* __restrict__ out4 = (const float4*)out_emb;

    // ---- producer: stage all 21 rows of batch-row r into buffer buf ----
    auto prefetch = [&](int r, int buf) {
#pragma unroll
        for (int i = 0; i < CWIN; i++) {
            int idx = __ldg(&ctx[r * CWIN + i]);
            cp16(&sh[warp][buf][i][lane], &in4[(size_t)idx * VEC + lane]);
        }
        {
            int t = __ldg(&tgt[r]);
            cp16(&sh[warp][buf][CWIN][lane], &out4[(size_t)t * VEC + lane]);
        }
#pragma unroll
        for (int k = 0; k < KNEG; k++) {
            int idx = __ldg(&neg[r * KNEG + k]);
            cp16(&sh[warp][buf][CWIN + 1 + k][lane], &out4[(size_t)idx * VEC + lane]);
        }
        asm volatile("cp.async.commit_group;\n" ::: "memory");
    };

    prefetch(rbase, 0);

    float loss = 0.f;
#pragma unroll
    for (int it = 0; it < ROWS_PER_WARP; it++) {
        if (it + 1 < ROWS_PER_WARP) {
            prefetch(rbase + it + 1, (it + 1) & 1);
            asm volatile("cp.async.wait_group 1;\n" ::: "memory");
        } else {
            asm volatile("cp.async.wait_group 0;\n" ::: "memory");
        }
        // Each lane reads exactly the 16B slots it wrote -> no warp sync needed.
        const int buf = it & 1;

        // context mean
        float4 a = sh[warp][buf][0][lane];
#pragma unroll
        for (int i = 1; i < CWIN; i++) {
            float4 v = sh[warp][buf][i][lane];
            a.x += v.x; a.y += v.y; a.z += v.z; a.w += v.w;
        }
        const float inv = 1.0f / (float)CWIN;
        a.x *= inv; a.y *= inv; a.z *= inv; a.w *= inv;

        // 11 dot-product partials (target = staged row CWIN, negs after)
        float s[NSCORE];
#pragma unroll
        for (int j = 0; j < NSCORE; j++) {
            float4 v = sh[warp][buf][CWIN + j][lane];
            s[j] = a.x * v.x + a.y * v.y + a.z * v.z + a.w * v.w;
        }

        // warp butterflies
#pragma unroll
        for (int j = 0; j < NSCORE; j++) {
#pragma unroll
            for (int off = 16; off > 0; off >>= 1)
                s[j] += __shfl_xor_sync(FULLM, s[j], off);
        }

        // loss terms spread across lanes 0..10, folded into lane 0
        // pos (j==0): log(sigmoid(+s)+eps) = log(1/(1+e^{-s}) + eps)
        // neg:        log(sigmoid(-s)+eps) = log(1/(1+e^{+s}) + eps)
        float term = 0.f;
        if (lane < NSCORE) {
            float x = (lane == 0) ? -s[0] : s[lane];
            term = __logf(__frcp_rn(1.0f + __expf(x)) + EPS);
        }
#pragma unroll
        for (int off = 8; off > 0; off >>= 1)
            term += __shfl_xor_sync(FULLM, term, off);
        loss += term;   // valid on lane 0
    }

    __shared__ float shloss[WARPS_PER_BLOCK];
    if (lane == 0) shloss[warp] = loss;
    __syncthreads();

    __shared__ bool amLast;
    if (threadIdx.x == 0) {
        float t = 0.f;
#pragma unroll
        for (int w = 0; w < WARPS_PER_BLOCK; w++) t += shloss[w];
        g_block_partial[blockIdx.x] = t;
        __threadfence();
        unsigned prev = atomicAdd(&g_done_counter, 1u);
        amLast = (prev == NBLOCKS - 1);
    }
    __syncthreads();

    // ---- last block: deterministic final reduction, fixed index order ----
    if (amLast) {
        float t = 0.f;
        for (int i = threadIdx.x; i < NBLOCKS; i += NTHREADS)
            t += __ldcg(&g_block_partial[i]);
#pragma unroll
        for (int off = 16; off > 0; off >>= 1)
            t += __shfl_xor_sync(FULLM, t, off);

        __shared__ float shf[WARPS_PER_BLOCK];
        if (lane == 0) shf[warp] = t;
        __syncthreads();
        if (threadIdx.x == 0) {
            float total = 0.f;
#pragma unroll
            for (int w = 0; w < WARPS_PER_BLOCK; w++) total += shf[w];
            out[0] = -total / (float)B_ROWS;
            g_done_counter = 0u;   // reset for next graph replay
        }
    }
}

extern "C" void kernel_launch(void* const* d_in, const int* in_sizes, int n_in,
                              void* d_out, int out_size)
{
    const int*   ctx     = (const int*)d_in[0];   // context [B, CWIN]
    const int*   tgt     = (const int*)d_in[1];   // target [B]
    const int*   neg     = (const int*)d_in[2];   // negatives [B, KNEG]
    const float* in_emb  = (const float*)d_in[3]; // [VOCAB, DIM]
    const float* out_emb = (const float*)d_in[4]; // [VOCAB, DIM]
    float*       out     = (float*)d_out;

    cbow_loss_kernel<<<NBLOCKS, NTHREADS>>>(ctx, tgt, neg, in_emb, out_emb, out);
}

// round 10
// speedup vs baseline: 1.1758x; 1.1758x over previous
#include <cuda_runtime.h>
#include <cuda_bf16.h>

#define B_ROWS   16384
#define CWIN     10
#define KNEG     10
#define NSCORE   (KNEG + 1)
#define DIM      128
#define VEC      (DIM / 4)          // 32 float4 per row -> 1 per lane
#define ROWS_PER_WARP  2
#define WARPS_PER_BLOCK 8
#define NTHREADS 256
#define NBLOCKS  592                 // 4 CTAs/SM x 148 SMs, persistent
#define TOTAL_WARPS (NBLOCKS * WARPS_PER_BLOCK)        // 4736
#define NPAIRS   (B_ROWS / ROWS_PER_WARP)              // 8192
#define EPS      1e-9f
#define FULLM    0xffffffffu

// Scratch for deterministic reduction (no allocations allowed).
__device__ float        g_block_partial[NBLOCKS];
__device__ unsigned int g_done_counter = 0u;

__global__ __launch_bounds__(NTHREADS, 4) void cbow_loss_kernel(
    const int*   __restrict__ ctx,      // [B, CWIN]
    const int*   __restrict__ tgt,      // [B]
    const int*   __restrict__ neg,      // [B, KNEG]
    const float* __restrict__ in_emb,   // [VOCAB, DIM]
    const float* __restrict__ out_emb,  // [VOCAB, DIM]
    float*       __restrict__ out)
{
    const int warp = threadIdx.x >> 5;
    const int lane = threadIdx.x & 31;
    const int gwid = blockIdx.x * WARPS_PER_BLOCK + warp;

    const float4* __restrict__ in4  = (const float4*)in_emb;
    const float4* __restrict__ out4 = (const float4*)out_emb;

    float loss = 0.f;   // per-lane partial (lane 0 accumulates real value)

    // persistent grid-stride over row pairs
    for (int p = gwid; p < NPAIRS; p += TOTAL_WARPS) {
        const int row0 = p * ROWS_PER_WARP;
        const int row1 = row0 + 1;

        // ---- context mean: two interleaved independent chains ----
        float4 a0 = make_float4(0.f, 0.f, 0.f, 0.f);
        float4 a1 = make_float4(0.f, 0.f, 0.f, 0.f);
#pragma unroll
        for (int i = 0; i < CWIN; i++) {
            int i0 = __ldg(&ctx[row0 * CWIN + i]);
            int i1 = __ldg(&ctx[row1 * CWIN + i]);
            float4 v0 = __ldg(&in4[(size_t)i0 * VEC + lane]);
            float4 v1 = __ldg(&in4[(size_t)i1 * VEC + lane]);
            a0.x += v0.x; a0.y += v0.y; a0.z += v0.z; a0.w += v0.w;
            a1.x += v1.x; a1.y += v1.y; a1.z += v1.z; a1.w += v1.w;
        }
        const float inv = 1.0f / (float)CWIN;
        a0.x *= inv; a0.y *= inv; a0.z *= inv; a0.w *= inv;
        a1.x *= inv; a1.y *= inv; a1.z *= inv; a1.w *= inv;

        // ---- 11 dot-product partial scores per row, interleaved ----
        float s0[NSCORE], s1[NSCORE];
        {
            int t0 = __ldg(&tgt[row0]);
            int t1 = __ldg(&tgt[row1]);
            float4 v0 = __ldg(&out4[(size_t)t0 * VEC + lane]);
            float4 v1 = __ldg(&out4[(size_t)t1 * VEC + lane]);
            s0[0] = a0.x * v0.x + a0.y * v0.y + a0.z * v0.z + a0.w * v0.w;
            s1[0] = a1.x * v1.x + a1.y * v1.y + a1.z * v1.z + a1.w * v1.w;
        }
#pragma unroll
        for (int k = 0; k < KNEG; k++) {
            int i0 = __ldg(&neg[row0 * KNEG + k]);
            int i1 = __ldg(&neg[row1 * KNEG + k]);
            float4 v0 = __ldg(&out4[(size_t)i0 * VEC + lane]);
            float4 v1 = __ldg(&out4[(size_t)i1 * VEC + lane]);
            s0[1 + k] = a0.x * v0.x + a0.y * v0.y + a0.z * v0.z + a0.w * v0.w;
            s1[1 + k] = a1.x * v1.x + a1.y * v1.y + a1.z * v1.z + a1.w * v1.w;
        }

        // ---- warp reductions (butterfly), both rows ----
#pragma unroll
        for (int j = 0; j < NSCORE; j++) {
#pragma unroll
            for (int off = 16; off > 0; off >>= 1) {
                s0[j] += __shfl_xor_sync(FULLM, s0[j], off);
                s1[j] += __shfl_xor_sync(FULLM, s1[j], off);
            }
        }

        // ---- loss terms: lanes 0..10 row0, lanes 16..26 row1 ----
        // pos (j==0): log(sigmoid(+s)+eps) = log(1/(1+e^{-s}) + eps)
        // neg:        log(sigmoid(-s)+eps) = log(1/(1+e^{+s}) + eps)
        float term = 0.f;
        {
            int lj = lane & 15;
            bool hi = (lane >= 16);
            if (lj < NSCORE) {
                float sv = hi ? s1[lj] : s0[lj];
                float x  = (lj == 0) ? -sv : sv;
                term = __logf(__frcp_rn(1.0f + __expf(x)) + EPS);
            }
        }
#pragma unroll
        for (int off = 8; off > 0; off >>= 1)
            term += __shfl_xor_sync(FULLM, term, off);
        term += __shfl_xor_sync(FULLM, term, 16);   // fold row1 into lane 0
        loss += term;                               // lane 0 holds pair loss
    }

    // ---- block accumulate (deterministic order) ----
    __shared__ float sh[WARPS_PER_BLOCK];
    if (lane == 0) sh[warp] = loss;
    __syncthreads();

    __shared__ bool amLast;
    if (threadIdx.x == 0) {
        float t = 0.f;
#pragma unroll
        for (int w = 0; w < WARPS_PER_BLOCK; w++) t += sh[w];
        g_block_partial[blockIdx.x] = t;
        __threadfence();
        unsigned prev = atomicAdd(&g_done_counter, 1u);
        amLast = (prev == NBLOCKS - 1);
    }
    __syncthreads();

    // ---- last block: deterministic final reduction, fixed index order ----
    if (amLast) {
        float t = 0.f;
        for (int i = threadIdx.x; i < NBLOCKS; i += NTHREADS)
            t += __ldcg(&g_block_partial[i]);
#pragma unroll
        for (int off = 16; off > 0; off >>= 1)
            t += __shfl_xor_sync(FULLM, t, off);

        __shared__ float shf[NTHREADS / 32];
        if (lane == 0) shf[warp] = t;
        __syncthreads();
        if (threadIdx.x == 0) {
            float total = 0.f;
#pragma unroll
            for (int w = 0; w < NTHREADS / 32; w++) total += shf[w];
            out[0] = -total / (float)B_ROWS;
            g_done_counter = 0u;   // reset for next graph replay
        }
    }
}

extern "C" void kernel_launch(void* const* d_in, const int* in_sizes, int n_in,
                              void* d_out, int out_size)
{
    const int*   ctx     = (const int*)d_in[0];   // context [B, CWIN]
    const int*   tgt     = (const int*)d_in[1];   // target [B]
    const int*   neg     = (const int*)d_in[2];   // negatives [B, KNEG]
    const float* in_emb  = (const float*)d_in[3]; // [VOCAB, DIM]
    const float* out_emb = (const float*)d_in[4]; // [VOCAB, DIM]
    float*       out     = (float*)d_out;

    cbow_loss_kernel<<<NBLOCKS, NTHREADS>>>(ctx, tgt, neg, in_emb, out_emb, out);
}